// round 9
// baseline (speedup 1.0000x reference)
#include <cuda_runtime.h>
#include <math.h>
#include <stdint.h>

#define NB 8
#define NS 1024
#define NE 1024
#define NH 16
#define ND 64
#define NM (NB*NS)

// ---------------- device-global scratch (allocation-free) ------------------
__device__ float g_qh[NB*NH*NS*ND];
__device__ float g_kh[NB*NH*NS*ND];
__device__ float g_vh[NB*NH*NS*ND];
__device__ float g_ctx[NB*NS*NE];
__device__ float g_qr[NM*NE];       // tf32-rounded inputs
__device__ float g_kr[NM*NE];
__device__ float g_vr[NM*NE];
__device__ float g_wqT[NH*ND*NE];   // [n=h*64+e][k], tf32-rounded
__device__ float g_wkT[NH*ND*NE];
__device__ float g_wvT[NH*ND*NE];
__device__ float g_woT[NE*NE];

__device__ __forceinline__ float tf32rna(float x) {
    uint32_t u;
    asm("cvt.rna.tf32.f32 %0, %1;" : "=r"(u) : "f"(x));
    return __uint_as_float(u);
}
__device__ __forceinline__ uint32_t smem_u32(const void* p) {
    uint32_t a;
    asm("{ .reg .u64 t; cvta.to.shared.u64 t, %1; cvt.u32.u64 %0, t; }" : "=r"(a) : "l"(p));
    return a;
}
__device__ __forceinline__ void cpa16(uint32_t dst, const void* src) {
    asm volatile("cp.async.cg.shared.global [%0], [%1], 16;" :: "r"(dst), "l"(src));
}
__device__ __forceinline__ void cpa_commit() {
    asm volatile("cp.async.commit_group;" ::: "memory");
}
template<int N> __device__ __forceinline__ void cpa_wait() {
    asm volatile("cp.async.wait_group %0;" :: "n"(N) : "memory");
}
__device__ __forceinline__ void barpair(int id) {
    asm volatile("bar.sync %0, 64;" :: "r"(id) : "memory");
}
__device__ __forceinline__ void mma16n8k8(float* d, const uint32_t* a, uint32_t b0, uint32_t b1) {
    asm volatile(
        "mma.sync.aligned.m16n8k8.row.col.f32.tf32.tf32.f32 "
        "{%0,%1,%2,%3}, {%4,%5,%6,%7}, {%8,%9}, {%0,%1,%2,%3};"
        : "+f"(d[0]), "+f"(d[1]), "+f"(d[2]), "+f"(d[3])
        : "r"(a[0]), "r"(a[1]), "r"(a[2]), "r"(a[3]), "r"(b0), "r"(b1));
}

// ---------------- GEMM: 128x128 tile, 3-stage cp.async, 1 sync/chunk -------
#define TSTRIDE 36
#define TILEF  (128*TSTRIDE)
#define STAGEF (2*TILEF)
#define GSTAGES 3
#define GSMEM_BYTES (GSTAGES*STAGEF*4)   // 110592 -> 2 CTAs/SM

__device__ __forceinline__ void gemm_body(
    const float* __restrict__ A, const float* __restrict__ BT,
    const float* __restrict__ bias, float* __restrict__ ob, int osel,
    float* sm)
{
    const uint32_t su = smem_u32(sm);
    const int tid  = threadIdx.x;
    const int wid  = tid >> 5;
    const int lane = tid & 31;
    const int g    = lane >> 2;
    const int t    = lane & 3;
    const int m0 = blockIdx.x * 128;
    const int n0 = blockIdx.y * 128;
    const int warp_m = (wid >> 2) * 64;
    const int warp_n = (wid & 3) * 32;

    const int lrow = tid >> 3;
    const int lc4  = tid & 7;

    auto issue = [&](int c, int s) {
        const int k0 = c * 32;
        const uint32_t base = su + s * (STAGEF * 4);
#pragma unroll
        for (int i = 0; i < 4; i++) {
            int row = lrow + i * 32;
            cpa16(base + (row * TSTRIDE + lc4 * 4) * 4,
                  A + (size_t)(m0 + row) * NE + k0 + lc4 * 4);
            cpa16(base + TILEF * 4 + (row * TSTRIDE + lc4 * 4) * 4,
                  BT + (size_t)(n0 + row) * NE + k0 + lc4 * 4);
        }
    };

    issue(0, 0); cpa_commit();
    issue(1, 1); cpa_commit();

    float d[4][4][4];
#pragma unroll
    for (int mi = 0; mi < 4; mi++)
#pragma unroll
        for (int ni = 0; ni < 4; ni++)
#pragma unroll
            for (int j = 0; j < 4; j++) d[mi][ni][j] = 0.f;

    for (int c = 0; c < 32; c++) {
        if (c < 31) cpa_wait<1>(); else cpa_wait<0>();
        __syncthreads();   // all warps done with chunk c-1; stage c landed
        // refill early: stage (c+2)%3 == (c-1)%3, consumed per the sync above
        if (c + 2 < 32) { issue(c + 2, (c + 2) % 3); cpa_commit(); }

        const int st = c % 3;
        const float* As = sm + st * STAGEF + (warp_m + g) * TSTRIDE;
        const float* Bs = sm + st * STAGEF + TILEF + (warp_n + g) * TSTRIDE;
#pragma unroll
        for (int ks = 0; ks < 4; ks++) {
            const int k0 = ks * 8 + t;
            uint32_t a[4][4];
#pragma unroll
            for (int mi = 0; mi < 4; mi++) {
                const float* ap = As + mi * 16 * TSTRIDE + k0;
                a[mi][0] = __float_as_uint(ap[0]);
                a[mi][1] = __float_as_uint(ap[8 * TSTRIDE]);
                a[mi][2] = __float_as_uint(ap[4]);
                a[mi][3] = __float_as_uint(ap[8 * TSTRIDE + 4]);
            }
#pragma unroll
            for (int ni = 0; ni < 4; ni++) {
                const float* bp = Bs + ni * 8 * TSTRIDE + k0;
                uint32_t b0 = __float_as_uint(bp[0]);
                uint32_t b1 = __float_as_uint(bp[4]);
#pragma unroll
                for (int mi = 0; mi < 4; mi++)
                    mma16n8k8(d[mi][ni], a[mi], b0, b1);
            }
        }
    }

#pragma unroll
    for (int mi = 0; mi < 4; mi++) {
#pragma unroll
        for (int ni = 0; ni < 4; ni++) {
            const int r0  = m0 + warp_m + mi * 16 + g;
            const int r1  = r0 + 8;
            const int col = n0 + warp_n + ni * 8 + t * 2;
            const float bx = bias[col], by = bias[col + 1];
            float2 v0, v1;
            v0.x = d[mi][ni][0] + bx; v0.y = d[mi][ni][1] + by;
            v1.x = d[mi][ni][2] + bx; v1.y = d[mi][ni][3] + by;
            if (osel < 3) {
                v0.x = tf32rna(v0.x); v0.y = tf32rna(v0.y);
                v1.x = tf32rna(v1.x); v1.y = tf32rna(v1.y);
                const int h = col >> 6, e = col & 63;
                float* d0 = ob + ((size_t)((r0 >> 10) * NH + h) * NS + (r0 & 1023)) * ND + e;
                float* d1 = ob + ((size_t)((r1 >> 10) * NH + h) * NS + (r1 & 1023)) * ND + e;
                *(float2*)d0 = v0;
                *(float2*)d1 = v1;
            } else {
                *(float2*)(ob + (size_t)r0 * NE + col) = v0;
                *(float2*)(ob + (size_t)r1 * NE + col) = v1;
            }
        }
    }
}

__global__ __launch_bounds__(256, 2) void proj_gemm(
    const float* __restrict__ bq, const float* __restrict__ bk,
    const float* __restrict__ bv)
{
    extern __shared__ float sm[];
    const int z = blockIdx.z;
    const float* A  = (z == 0) ? g_qr  : (z == 1) ? g_kr  : g_vr;
    const float* BT = (z == 0) ? g_wqT : (z == 1) ? g_wkT : g_wvT;
    const float* bias = (z == 0) ? bq : (z == 1) ? bk : bv;
    float* ob = (z == 0) ? g_qh : (z == 1) ? g_kh : g_vh;
    gemm_body(A, BT, bias, ob, z, sm);
}

__global__ __launch_bounds__(256, 2) void out_gemm(
    const float* __restrict__ bo, float* __restrict__ out)
{
    extern __shared__ float sm[];
    gemm_body(g_ctx, g_woT, bo, out, 3, sm);
}

// ---------------- attention: kv-split warp pairs, tf32 mma flash ------------
// 8 warps: mgrp = wid>>1 owns q-rows [mgrp*32, +32); nh = wid&1 owns kv half.
#define KSTR 68
#define VSTR 72
#define QPF  (128*KSTR)                 // Q tile, reused as P and O-merge buffer
#define KVF  (64*KSTR + 64*VSTR)        // per KV stage
#define AKVSTG 3
#define XOFF (QPF + AKVSTG*KVF)         // exchange buffers (floats)
#define ASMEM_BYTES ((XOFF + 512)*4)    // 144384

__global__ __launch_bounds__(256, 1) void attn_mma()
{
    extern __shared__ float smf[];
    const uint32_t su = smem_u32(smf);
    const int tid = threadIdx.x, wid = tid >> 5, lane = tid & 31;
    const int g = lane >> 2, t = lane & 3;
    const int mgrp = wid >> 1, nh = wid & 1;
    const int bh = blockIdx.y;
    const int s0 = blockIdx.x * 128;
    const float* Qp = g_qh + (size_t)bh * NS * ND;
    const float* Kp = g_kh + (size_t)bh * NS * ND;
    const float* Vp = g_vh + (size_t)bh * NS * ND;
    float* xm = smf + XOFF;          // [ (mgrp*2+nh)*32 + row ]
    float* xs = xm + 256;

    const int lkv = tid >> 4;
    const int lc4 = tid & 15;

    auto issue_kv = [&](int kt, int st) {
        const uint32_t kB = su + QPF * 4 + st * (KVF * 4);
        const uint32_t vB = kB + 64 * KSTR * 4;
        const float* Ks = Kp + (size_t)kt * 64 * ND;
        const float* Vs = Vp + (size_t)kt * 64 * ND;
#pragma unroll
        for (int i = 0; i < 4; i++) {
            int kv = lkv + i * 16;
            cpa16(kB + (kv * KSTR + lc4 * 4) * 4, Ks + (size_t)kv * ND + lc4 * 4);
            cpa16(vB + (kv * VSTR + lc4 * 4) * 4, Vs + (size_t)kv * ND + lc4 * 4);
        }
    };

    issue_kv(0, 0); cpa_commit();
    issue_kv(1, 1); cpa_commit();

    // Q tile -> smem
#pragma unroll
    for (int i = 0; i < 8; i++) {
        int idx = tid + i * 256;
        int row = idx >> 4, c4 = idx & 15;
        *(float4*)(smf + row * KSTR + c4 * 4) =
            *(const float4*)(Qp + (size_t)(s0 + row) * ND + c4 * 4);
    }
    __syncthreads();

    // persistent Q fragments: 2 m-frags (rows mgrp*32 + mf*16 + {g, g+8})
    uint32_t qf[8][2][4];
#pragma unroll
    for (int mf = 0; mf < 2; mf++) {
        const float* qp = smf + (mgrp * 32 + mf * 16 + g) * KSTR;
#pragma unroll
        for (int ks = 0; ks < 8; ks++) {
            qf[ks][mf][0] = __float_as_uint(qp[ks * 8 + t]);
            qf[ks][mf][1] = __float_as_uint(qp[8 * KSTR + ks * 8 + t]);
            qf[ks][mf][2] = __float_as_uint(qp[ks * 8 + t + 4]);
            qf[ks][mf][3] = __float_as_uint(qp[8 * KSTR + ks * 8 + t + 4]);
        }
    }

    float o[2][8][4];
#pragma unroll
    for (int mf = 0; mf < 2; mf++)
#pragma unroll
        for (int ni = 0; ni < 8; ni++)
#pragma unroll
            for (int j = 0; j < 4; j++) o[mf][ni][j] = 0.f;
    float mS[2][2], lS[2][2];
#pragma unroll
    for (int mf = 0; mf < 2; mf++) {
        mS[mf][0] = -1e30f; mS[mf][1] = -1e30f;
        lS[mf][0] = 0.f;    lS[mf][1] = 0.f;
    }
    const float scale = 0.125f;
    const int xown = (mgrp * 2 + nh) * 32;
    const int xoth = (mgrp * 2 + (nh ^ 1)) * 32;

    for (int kt = 0; kt < 16; kt++) {
        if (kt < 15) cpa_wait<1>(); else cpa_wait<0>();
        __syncthreads();
        if (kt + 2 < 16) { issue_kv(kt + 2, (kt + 2) % 3); cpa_commit(); }

        const float* sK = smf + QPF + (kt % 3) * KVF;
        const float* sV = sK + 64 * KSTR;

        // S = Q @ K^T over own kv half (cols nh*32 .. +32)
        float s[2][4][4];
#pragma unroll
        for (int mf = 0; mf < 2; mf++)
#pragma unroll
            for (int ni = 0; ni < 4; ni++)
#pragma unroll
                for (int j = 0; j < 4; j++) s[mf][ni][j] = 0.f;
#pragma unroll
        for (int ks = 0; ks < 8; ks++) {
            const float* kp = sK + ks * 8 + t;
#pragma unroll
            for (int ni = 0; ni < 4; ni++) {
                const int krow = nh * 32 + ni * 8 + g;
                uint32_t b0 = __float_as_uint(kp[krow * KSTR]);
                uint32_t b1 = __float_as_uint(kp[krow * KSTR + 4]);
                mma16n8k8(s[0][ni], qf[ks][0], b0, b1);
                mma16n8k8(s[1][ni], qf[ks][1], b0, b1);
            }
        }

        // local row maxes (raw), quad-reduced
        float mx[2][2];
#pragma unroll
        for (int mf = 0; mf < 2; mf++) {
            float mxA = -1e30f, mxB = -1e30f;
#pragma unroll
            for (int ni = 0; ni < 4; ni++) {
                mxA = fmaxf(mxA, fmaxf(s[mf][ni][0], s[mf][ni][1]));
                mxB = fmaxf(mxB, fmaxf(s[mf][ni][2], s[mf][ni][3]));
            }
            mxA = fmaxf(mxA, __shfl_xor_sync(0xffffffffu, mxA, 1));
            mxA = fmaxf(mxA, __shfl_xor_sync(0xffffffffu, mxA, 2));
            mxB = fmaxf(mxB, __shfl_xor_sync(0xffffffffu, mxB, 1));
            mxB = fmaxf(mxB, __shfl_xor_sync(0xffffffffu, mxB, 2));
            mx[mf][0] = mxA; mx[mf][1] = mxB;
            if (t == 0) {
                xm[xown + mf * 16 + g]     = mxA;
                xm[xown + mf * 16 + 8 + g] = mxB;
            }
        }
        barpair(1 + mgrp);

        float alph[2][2], lsum[2][2];
#pragma unroll
        for (int mf = 0; mf < 2; mf++) {
            float gA = fmaxf(mx[mf][0], xm[xoth + mf * 16 + g]);
            float gB = fmaxf(mx[mf][1], xm[xoth + mf * 16 + 8 + g]);
            float mAn = fmaxf(mS[mf][0], gA * scale);
            float mBn = fmaxf(mS[mf][1], gB * scale);
            alph[mf][0] = __expf(mS[mf][0] - mAn);
            alph[mf][1] = __expf(mS[mf][1] - mBn);
            mS[mf][0] = mAn; mS[mf][1] = mBn;
            float sumA = 0.f, sumB = 0.f;
#pragma unroll
            for (int ni = 0; ni < 4; ni++) {
                s[mf][ni][0] = __expf(s[mf][ni][0] * scale - mAn);
                s[mf][ni][1] = __expf(s[mf][ni][1] * scale - mAn);
                s[mf][ni][2] = __expf(s[mf][ni][2] * scale - mBn);
                s[mf][ni][3] = __expf(s[mf][ni][3] * scale - mBn);
                sumA += s[mf][ni][0] + s[mf][ni][1];
                sumB += s[mf][ni][2] + s[mf][ni][3];
            }
            sumA += __shfl_xor_sync(0xffffffffu, sumA, 1);
            sumA += __shfl_xor_sync(0xffffffffu, sumA, 2);
            sumB += __shfl_xor_sync(0xffffffffu, sumB, 1);
            sumB += __shfl_xor_sync(0xffffffffu, sumB, 2);
            lsum[mf][0] = sumA; lsum[mf][1] = sumB;
            if (t == 0) {
                xs[xown + mf * 16 + g]     = sumA;
                xs[xown + mf * 16 + 8 + g] = sumB;
            }
        }
        barpair(1 + mgrp);

#pragma unroll
        for (int mf = 0; mf < 2; mf++) {
            lS[mf][0] = lS[mf][0] * alph[mf][0] + lsum[mf][0] + xs[xoth + mf * 16 + g];
            lS[mf][1] = lS[mf][1] * alph[mf][1] + lsum[mf][1] + xs[xoth + mf * 16 + 8 + g];
#pragma unroll
            for (int ni = 0; ni < 8; ni++) {
                o[mf][ni][0] *= alph[mf][0]; o[mf][ni][1] *= alph[mf][0];
                o[mf][ni][2] *= alph[mf][1]; o[mf][ni][3] *= alph[mf][1];
            }
        }

        // publish P (tf32) into Q buffer: rows mgrp*32.., cols nh*32..
        __syncwarp();
#pragma unroll
        for (int mf = 0; mf < 2; mf++) {
            float* pr = smf + (mgrp * 32 + mf * 16 + g) * KSTR + nh * 32;
#pragma unroll
            for (int ni = 0; ni < 4; ni++) {
                float2 v0; v0.x = tf32rna(s[mf][ni][0]); v0.y = tf32rna(s[mf][ni][1]);
                float2 v1; v1.x = tf32rna(s[mf][ni][2]); v1.y = tf32rna(s[mf][ni][3]);
                *(float2*)(pr + ni * 8 + 2 * t) = v0;
                *(float2*)(pr + 8 * KSTR + ni * 8 + 2 * t) = v1;
            }
        }
        __syncwarp();

        // O += P(own half) @ V(own half rows, all 64 cols)
#pragma unroll
        for (int ks = 0; ks < 4; ks++) {
            uint32_t a[2][4];
#pragma unroll
            for (int mf = 0; mf < 2; mf++) {
                const float* pr = smf + (mgrp * 32 + mf * 16 + g) * KSTR + nh * 32;
                a[mf][0] = __float_as_uint(pr[ks * 8 + t]);
                a[mf][1] = __float_as_uint(pr[8 * KSTR + ks * 8 + t]);
                a[mf][2] = __float_as_uint(pr[ks * 8 + t + 4]);
                a[mf][3] = __float_as_uint(pr[8 * KSTR + ks * 8 + t + 4]);
            }
            const float* vp = sV + (nh * 32 + ks * 8 + t) * VSTR;
#pragma unroll
            for (int ni = 0; ni < 8; ni++) {
                uint32_t b0 = __float_as_uint(vp[ni * 8 + g]);
                uint32_t b1 = __float_as_uint(vp[4 * VSTR + ni * 8 + g]);
                mma16n8k8(o[0][ni], a[0], b0, b1);
                mma16n8k8(o[1][ni], a[1], b0, b1);
            }
        }
    }

    // merge kv halves: nh==1 stages its partial O in the Q/P buffer
    __syncthreads();
    if (nh == 1) {
#pragma unroll
        for (int mf = 0; mf < 2; mf++) {
            float* pr = smf + (mgrp * 32 + mf * 16 + g) * KSTR;
#pragma unroll
            for (int ni = 0; ni < 8; ni++) {
                float2 v0; v0.x = o[mf][ni][0]; v0.y = o[mf][ni][1];
                float2 v1; v1.x = o[mf][ni][2]; v1.y = o[mf][ni][3];
                *(float2*)(pr + ni * 8 + 2 * t) = v0;
                *(float2*)(pr + 8 * KSTR + ni * 8 + 2 * t) = v1;
            }
        }
    }
    __syncthreads();
    if (nh == 0) {
        const int b = bh >> 4, h = bh & 15;
#pragma unroll
        for (int mf = 0; mf < 2; mf++) {
            const float iA = 1.f / lS[mf][0], iB = 1.f / lS[mf][1];
            const float* pr = smf + (mgrp * 32 + mf * 16 + g) * KSTR;
            const int rA = s0 + mgrp * 32 + mf * 16 + g, rB = rA + 8;
            float* dA = g_ctx + (size_t)(b * NS + rA) * NE + h * 64;
            float* dB = g_ctx + (size_t)(b * NS + rB) * NE + h * 64;
#pragma unroll
            for (int ni = 0; ni < 8; ni++) {
                float2 p0 = *(const float2*)(pr + ni * 8 + 2 * t);
                float2 p1 = *(const float2*)(pr + 8 * KSTR + ni * 8 + 2 * t);
                float2 vA, vB2;
                vA.x  = tf32rna((o[mf][ni][0] + p0.x) * iA);
                vA.y  = tf32rna((o[mf][ni][1] + p0.y) * iA);
                vB2.x = tf32rna((o[mf][ni][2] + p1.x) * iB);
                vB2.y = tf32rna((o[mf][ni][3] + p1.y) * iB);
                *(float2*)(dA + ni * 8 + 2 * t) = vA;
                *(float2*)(dB + ni * 8 + 2 * t) = vB2;
            }
        }
    }
}

// ---------------- small prep kernels ----------------------------------------
__global__ void round_kernel(const float* __restrict__ q, const float* __restrict__ k,
                             const float* __restrict__ v, int n4)
{
    const int z = blockIdx.z;
    const float* in = (z == 0) ? q : (z == 1) ? k : v;
    float* out = (z == 0) ? g_qr : (z == 1) ? g_kr : g_vr;
    int i = blockIdx.x * blockDim.x + threadIdx.x;
    for (; i < n4; i += gridDim.x * blockDim.x) {
        float4 w = ((const float4*)in)[i];
        w.x = tf32rna(w.x); w.y = tf32rna(w.y);
        w.z = tf32rna(w.z); w.w = tf32rna(w.w);
        ((float4*)out)[i] = w;
    }
}

__global__ void transpose_all(const float* __restrict__ Wq, const float* __restrict__ Wk,
                              const float* __restrict__ Wv, const float* __restrict__ Wo)
{
    __shared__ float tbuf[32][33];
    const int z = blockIdx.z;
    const float* I;
    float* O;
    int R, C, c0, r0;
    if (z < 3) {
        const float* W = (z == 0) ? Wq : (z == 1) ? Wk : Wv;
        float* out = (z == 0) ? g_wqT : (z == 1) ? g_wkT : g_wvT;
        const int h = blockIdx.x >> 1;
        R = NE; C = ND;
        I = W   + (size_t)h * R * C;
        O = out + (size_t)h * R * C;
        c0 = (blockIdx.x & 1) * 32;
        r0 = blockIdx.y * 32;
    } else {
        R = NE; C = NE;
        I = Wo; O = g_woT;
        c0 = blockIdx.x * 32;
        r0 = blockIdx.y * 32;
    }
#pragma unroll
    for (int j = threadIdx.y; j < 32; j += 8)
        tbuf[j][threadIdx.x] = I[(size_t)(r0 + j) * C + c0 + threadIdx.x];
    __syncthreads();
#pragma unroll
    for (int j = threadIdx.y; j < 32; j += 8)
        O[(size_t)(c0 + j) * R + r0 + threadIdx.x] = tf32rna(tbuf[threadIdx.x][j]);
}

// ---------------------------------------------------------------------------
extern "C" void kernel_launch(void* const* d_in, const int* in_sizes, int n_in,
                              void* d_out, int out_size)
{
    const float* q  = (const float*)d_in[0];
    const float* k  = (const float*)d_in[1];
    const float* v  = (const float*)d_in[2];
    const float* Wq = (const float*)d_in[3];
    const float* bq = (const float*)d_in[4];
    const float* Wk = (const float*)d_in[5];
    const float* bk = (const float*)d_in[6];
    const float* Wv = (const float*)d_in[7];
    const float* bv = (const float*)d_in[8];
    const float* Wo = (const float*)d_in[9];
    const float* bo = (const float*)d_in[10];
    float* out = (float*)d_out;

    cudaFuncSetAttribute(proj_gemm, cudaFuncAttributeMaxDynamicSharedMemorySize, GSMEM_BYTES);
    cudaFuncSetAttribute(out_gemm,  cudaFuncAttributeMaxDynamicSharedMemorySize, GSMEM_BYTES);
    cudaFuncSetAttribute(attn_mma,  cudaFuncAttributeMaxDynamicSharedMemorySize, ASMEM_BYTES);

    const int n4 = NM * NE / 4;
    round_kernel<<<dim3(512, 1, 3), 256>>>(q, k, v, n4);

    transpose_all<<<dim3(32, 32, 4), dim3(32, 8)>>>(Wq, Wk, Wv, Wo);

    proj_gemm<<<dim3(NM / 128, NE / 128, 3), 256, GSMEM_BYTES>>>(bq, bk, bv);

    attn_mma<<<dim3(NS / 128, NB * NH), 256, ASMEM_BYTES>>>();

    out_gemm<<<dim3(NM / 128, NE / 128), 256, GSMEM_BYTES>>>(bo, out);
}